// round 3
// baseline (speedup 1.0000x reference)
#include <cuda_runtime.h>
#include <math.h>

#define B   128
#define T   256
#define H   512
#define H4  2048
#define V   128
#define LW  32
#define SOS 1
#define BH  (B*H)      // 65536
#define NBLK 128
#define NTHR 256

// ---------------- device scratch (static) ----------------
__device__ float g_enc0[(size_t)B*T*2*H];   // [b][t][dir*H+u]
__device__ float g_enc1[(size_t)B*T*2*H];   // [b][t][dir*H+u]
__device__ float g_h0[2*2*BH];              // [parity][dir][b][u]
__device__ float g_h1[2*2*BH];
__device__ float g_c0[2*BH];                // [dir][b][u] (block-owned, no parity)
__device__ float g_c1[2*BH];
__device__ float g_dech[2*2*BH];            // [parity][l][b][u]
__device__ float g_decc[2*BH];              // [l][b][u]
__device__ float g_query[B*2*H];
__device__ float g_ctx[B*2*H];
__device__ float g_comb[B*H];
__device__ int   g_tok[B];

__device__ unsigned g_cnt = 0;
__device__ volatile unsigned g_gen = 0;

// ---------------- software grid barrier (all NBLK blocks resident) ----------------
__device__ __forceinline__ void gbar(unsigned &gen)
{
    __syncthreads();
    if (threadIdx.x == 0) {
        __threadfence();
        unsigned t = atomicAdd(&g_cnt, 1u);
        if (t == NBLK - 1u) {
            atomicExch(&g_cnt, 0u);
            __threadfence();
            g_gen = gen + 1u;
        } else {
            while (g_gen == gen) {}
            __threadfence();
        }
    }
    __syncthreads();
    gen++;
}

// ---------------- gate-split GEMM: acc += A[64 rows] x W columns {g*512+u0..+16, g=0..3}
// 256 thr, 4x4 micro-tile over a 64(M) x 64(4 gates x 16) tile.
__device__ __forceinline__ void mm_gate(
    float acc[4][4],
    const float* __restrict__ A, long lda, const int* __restrict__ idx, int m0,
    const float* __restrict__ W, int u0, int K,
    float (* __restrict__ As)[64], float (* __restrict__ Bs)[64])
{
    const int tid = threadIdx.x;
    const int ty = tid >> 4, tx = tid & 15;
    const int am = tid >> 2, ak = (tid & 3) * 4;
    long arow = idx ? (long)idx[m0 + am] : (long)(m0 + am);
    const float* Ab = A + arow * lda + ak;
    const int bk  = tid >> 4;
    const int btx = tid & 15;
    const int bcol = (btx >> 2) * H + u0 + (btx & 3) * 4;

    for (int k0 = 0; k0 < K; k0 += 16) {
        float4 av = *(const float4*)(Ab + k0);
        As[ak+0][am] = av.x; As[ak+1][am] = av.y;
        As[ak+2][am] = av.z; As[ak+3][am] = av.w;
        *(float4*)&Bs[bk][btx*4] = *(const float4*)(W + (long)(k0 + bk) * H4 + bcol);
        __syncthreads();
        #pragma unroll
        for (int k = 0; k < 16; k++) {
            float4 a = *(const float4*)&As[k][ty*4];
            float4 b = *(const float4*)&Bs[k][tx*4];
            float aa[4] = {a.x,a.y,a.z,a.w};
            float bb[4] = {b.x,b.y,b.z,b.w};
            #pragma unroll
            for (int i = 0; i < 4; i++)
                #pragma unroll
                for (int j = 0; j < 4; j++)
                    acc[i][j] = fmaf(aa[i], bb[j], acc[i][j]);
        }
        __syncthreads();
    }
}

// ---------------- plain 64x64-tile GEMM: acc += A x W[:, n0..n0+64) ----------------
__device__ __forceinline__ void mm_plain(
    float acc[4][4],
    const float* __restrict__ A, long lda, int m0,
    const float* __restrict__ W, int ldw, int K, int n0,
    float (* __restrict__ As)[64], float (* __restrict__ Bs)[64])
{
    const int tid = threadIdx.x;
    const int ty = tid >> 4, tx = tid & 15;
    const int am = tid >> 2, ak = (tid & 3) * 4;
    const float* Ab = A + (long)(m0 + am) * lda + ak;
    const int bk  = tid >> 4;
    const int btx = tid & 15;

    for (int k0 = 0; k0 < K; k0 += 16) {
        float4 av = *(const float4*)(Ab + k0);
        As[ak+0][am] = av.x; As[ak+1][am] = av.y;
        As[ak+2][am] = av.z; As[ak+3][am] = av.w;
        *(float4*)&Bs[bk][btx*4] = *(const float4*)(W + (long)(k0 + bk) * ldw + n0 + btx*4);
        __syncthreads();
        #pragma unroll
        for (int k = 0; k < 16; k++) {
            float4 a = *(const float4*)&As[k][ty*4];
            float4 b = *(const float4*)&Bs[k][tx*4];
            float aa[4] = {a.x,a.y,a.z,a.w};
            float bb[4] = {b.x,b.y,b.z,b.w};
            #pragma unroll
            for (int i = 0; i < 4; i++)
                #pragma unroll
                for (int j = 0; j < 4; j++)
                    acc[i][j] = fmaf(aa[i], bb[j], acc[i][j]);
        }
        __syncthreads();
    }
}

__device__ __forceinline__ float sigm(float v) { return 1.f/(1.f + expf(-v)); }

// ---------------- the single persistent kernel ----------------
__global__ void __launch_bounds__(NTHR, 1)
traj_kernel(const float* __restrict__ x,
            const float* __restrict__ w0ih, const float* __restrict__ w0hh, const float* __restrict__ b0,
            const float* __restrict__ w1ih, const float* __restrict__ w1hh, const float* __restrict__ b1,
            const float* __restrict__ dWih, const float* __restrict__ dWhh, const float* __restrict__ db,
            const float* __restrict__ emb,
            const float* __restrict__ Wq,  const float* __restrict__ bq,
            const float* __restrict__ Wc,  const float* __restrict__ bc,
            const float* __restrict__ Wf,  const float* __restrict__ bfv,
            float* __restrict__ out)
{
    __shared__ float As[16][64];
    __shared__ float Bs[16][64];
    __shared__ float Gs[64][65];

    const int blk = blockIdx.x;
    const int tid = threadIdx.x;
    unsigned gen = 0;

    // ---- init: zero states (parity-0 h buffers + c) ----
    for (int i = blk*NTHR + tid; i < 2*BH; i += NBLK*NTHR) {
        g_h0[i] = 0.f; g_h1[i] = 0.f;
        g_c0[i] = 0.f; g_c1[i] = 0.f;
    }
    gbar(gen);

    // ---- encoder: layer then timestep loops ----
    for (int layer = 0; layer < 2; layer++) {
        const int dir = blk >> 6;
        const int m0  = ((blk >> 5) & 1) * 64;
        const int u0  = (blk & 31) * 16;
        const int ty = tid >> 4, tx = tid & 15;
        for (int tf = 0; tf < T; tf++) {
            const int t = dir ? (T - 1 - tf) : tf;
            const int po = (tf & 1) * 2 * BH;        // old parity offset
            const int pn = ((tf + 1) & 1) * 2 * BH;  // new parity offset
            float acc[4][4] = {};
            const float* bias_d;
            if (layer == 0) {
                mm_gate(acc, g_h0 + po + (long)dir*BH, H, nullptr, m0,
                        w0hh + (long)dir*H*H4, u0, H, As, Bs);
                bias_d = b0 + (long)dir*H4;
            } else {
                mm_gate(acc, g_enc0 + (long)t*2*H, (long)T*2*H, nullptr, m0,
                        w1ih + (long)dir*(2*H)*H4, u0, 2*H, As, Bs);
                mm_gate(acc, g_h1 + po + (long)dir*BH, H, nullptr, m0,
                        w1hh + (long)dir*H*H4, u0, H, As, Bs);
                bias_d = b1 + (long)dir*H4;
            }
            // store gates (+bias, +x for layer0) to shared
            #pragma unroll
            for (int i = 0; i < 4; i++) {
                int ml = ty*4 + i;
                float x0 = 0.f, x1 = 0.f;
                if (layer == 0) {
                    int b = m0 + ml;
                    x0 = x[((long)b*T + t)*2 + 0];
                    x1 = x[((long)b*T + t)*2 + 1];
                }
                #pragma unroll
                for (int j = 0; j < 4; j++) {
                    int cg = tx*4 + j;
                    int col = (cg >> 4)*H + u0 + (cg & 15);
                    float v = acc[i][j] + bias_d[col];
                    if (layer == 0) {
                        const float* Wi = w0ih + (long)dir*2*H4;
                        v += x0*Wi[col] + x1*Wi[H4 + col];
                    }
                    Gs[ml][cg] = v;
                }
            }
            __syncthreads();
            // fused LSTM update for this block's (m,u) tile
            float* hN = (layer ? g_h1 : g_h0) + pn + (long)dir*BH;
            float* cB = (layer ? g_c1 : g_c0) + (long)dir*BH;
            float* y  = layer ? g_enc1 : g_enc0;
            #pragma unroll
            for (int r = 0; r < 4; r++) {
                int p  = tid + r*NTHR;
                int ml = p >> 4, ui = p & 15;
                float gi = Gs[ml][ui],      gf = Gs[ml][16+ui];
                float gg = Gs[ml][32+ui],   go = Gs[ml][48+ui];
                int b = m0 + ml, u = u0 + ui;
                long su = (long)b*H + u;
                float cn = sigm(gf)*cB[su] + sigm(gi)*tanhf(gg);
                float hn = sigm(go)*tanhf(cn);
                cB[su] = cn;
                hN[su] = hn;
                y[((long)b*T + t)*(2*H) + dir*H + u] = hn;
            }
            gbar(gen);
        }
    }

    // ---- decoder init: sum fwd+bwd final states (parity 0 after T=256 steps) ----
    for (int i = blk*NTHR + tid; i < BH; i += NBLK*NTHR) {
        g_dech[i]      = g_h0[i] + g_h0[BH + i];
        g_decc[i]      = g_c0[i] + g_c0[BH + i];
        g_dech[BH + i] = g_h1[i] + g_h1[BH + i];
        g_decc[BH + i] = g_c1[i] + g_c1[BH + i];
    }
    if (blk == 0 && tid < B) g_tok[tid] = SOS;
    gbar(gen);

    const int ty = tid >> 4, tx = tid & 15;

    // ---- decoder: 32 greedy steps ----
    for (int s = 0; s < LW; s++) {
        const int po = (s & 1) * 2 * BH;
        const int pn = ((s + 1) & 1) * 2 * BH;

        // LSTM layers 0 and 1 (gates + fused update)
        for (int l = 0; l < 2; l++) {
            if (blk < 64) {
                const int m0 = (blk >> 5) * 64;
                const int u0 = (blk & 31) * 16;
                float acc[4][4] = {};
                if (l == 0)
                    mm_gate(acc, emb, H, g_tok, m0, dWih, u0, H, As, Bs);
                else
                    mm_gate(acc, g_dech + pn, H, nullptr, m0, dWih + (long)H*H4, u0, H, As, Bs);
                mm_gate(acc, g_dech + po + (long)l*BH, H, nullptr, m0,
                        dWhh + (long)l*H*H4, u0, H, As, Bs);
                const float* bias_d = db + (long)l*H4;
                #pragma unroll
                for (int i = 0; i < 4; i++) {
                    int ml = ty*4 + i;
                    #pragma unroll
                    for (int j = 0; j < 4; j++) {
                        int cg = tx*4 + j;
                        int col = (cg >> 4)*H + u0 + (cg & 15);
                        Gs[ml][cg] = acc[i][j] + bias_d[col];
                    }
                }
                __syncthreads();
                float* hN = g_dech + pn + (long)l*BH;
                float* cB = g_decc + (long)l*BH;
                #pragma unroll
                for (int r = 0; r < 4; r++) {
                    int p  = tid + r*NTHR;
                    int ml = p >> 4, ui = p & 15;
                    float gi = Gs[ml][ui],    gf = Gs[ml][16+ui];
                    float gg = Gs[ml][32+ui], go = Gs[ml][48+ui];
                    long su = (long)(m0 + ml)*H + (u0 + ui);
                    float cn = sigm(gf)*cB[su] + sigm(gi)*tanhf(gg);
                    float hn = sigm(go)*tanhf(cn);
                    cB[su] = cn;
                    hN[su] = hn;
                }
            }
            gbar(gen);
        }

        // query = h1_new @ Wq + bq   (C: [128 x 1024])
        if (blk < 32) {
            const int m0 = (blk >> 4) * 64;
            const int n0 = (blk & 15) * 64;
            float acc[4][4] = {};
            mm_plain(acc, g_dech + pn + BH, H, m0, Wq, 2*H, H, n0, As, Bs);
            #pragma unroll
            for (int i = 0; i < 4; i++) {
                int m = m0 + ty*4 + i;
                #pragma unroll
                for (int j = 0; j < 4; j++) {
                    int n = n0 + tx*4 + j;
                    g_query[(long)m*(2*H) + n] = acc[i][j] + bq[n];
                }
            }
        }
        gbar(gen);

        // attention per batch (all 128 blocks)
        {
            const int b = blk;
            float* sm = &Gs[0][0];            // reuse Gs: qs[1024] sc[256] red[256]
            float* qs  = sm;
            float* sc  = sm + 1024;
            float* red = sm + 1280;
            for (int e = tid; e < 2*H; e += NTHR) qs[e] = g_query[(long)b*2*H + e];
            __syncthreads();
            const int warp = tid >> 5, lane = tid & 31;
            for (int tb = 0; tb < T; tb += 8) {
                int t = tb + warp;
                const float* row = g_enc1 + ((long)b*T + t)*(2*H);
                float p = 0.f;
                for (int e = lane; e < 2*H; e += 32) p = fmaf(row[e], qs[e], p);
                #pragma unroll
                for (int o = 16; o; o >>= 1) p += __shfl_xor_sync(0xffffffffu, p, o);
                if (lane == 0) sc[t] = p;
            }
            __syncthreads();
            float v = sc[tid];
            red[tid] = v; __syncthreads();
            for (int o = 128; o; o >>= 1) {
                if (tid < o) red[tid] = fmaxf(red[tid], red[tid + o]);
                __syncthreads();
            }
            float mx = red[0]; __syncthreads();
            float e = expf(v - mx);
            red[tid] = e; __syncthreads();
            for (int o = 128; o; o >>= 1) {
                if (tid < o) red[tid] += red[tid + o];
                __syncthreads();
            }
            float a = e / red[0];
            sc[tid] = a;
            out[786432 + ((long)b*T + tid)*LW + s] = a;
            __syncthreads();
            for (int ec = tid; ec < 2*H; ec += NTHR) {
                float accv = 0.f;
                const float* base = g_enc1 + ((long)b*T)*(2*H) + ec;
                for (int t = 0; t < T; t++) accv = fmaf(sc[t], base[(long)t*2*H], accv);
                g_ctx[(long)b*2*H + ec] = accv;
            }
        }
        gbar(gen);

        // combined = [h1 | ctx] @ Wc + bc   (C: [128 x 512])
        if (blk < 16) {
            const int m0 = (blk >> 3) * 64;
            const int n0 = (blk & 7) * 64;
            float acc[4][4] = {};
            mm_plain(acc, g_dech + pn + BH, H, m0, Wc, H, H, n0, As, Bs);
            mm_plain(acc, g_ctx, 2*H, m0, Wc + (long)H*H, H, 2*H, n0, As, Bs);
            #pragma unroll
            for (int i = 0; i < 4; i++) {
                int m = m0 + ty*4 + i;
                #pragma unroll
                for (int j = 0; j < 4; j++) {
                    int n = n0 + tx*4 + j;
                    g_comb[(long)m*H + n] = acc[i][j] + bc[n];
                }
            }
        }
        gbar(gen);

        // logits + argmax (block = batch)
        {
            const int b = blk;
            float* sm = &Gs[0][0];
            float* cs = sm;            // [512]
            float* sv = sm + 512;      // [128]
            int*   si = (int*)(sm + 640);
            for (int k = tid; k < H; k += NTHR) cs[k] = g_comb[(long)b*H + k];
            __syncthreads();
            if (tid < V) {
                float acc = bfv[tid];
                for (int k = 0; k < H; k++) acc = fmaf(cs[k], Wf[(long)k*V + tid], acc);
                out[((long)b*LW + s)*V + tid] = acc;
                sv[tid] = acc; si[tid] = tid;
            }
            __syncthreads();
            for (int o = 64; o; o >>= 1) {
                if (tid < o) {
                    float v2 = sv[tid + o]; int i2 = si[tid + o];
                    if (v2 > sv[tid] || (v2 == sv[tid] && i2 < si[tid])) {
                        sv[tid] = v2; si[tid] = i2;
                    }
                }
                __syncthreads();
            }
            if (tid == 0) g_tok[b] = si[0];
        }
        gbar(gen);
    }

    // ---- final states: hF at 524288, cF at 655360 (final parity = 0) ----
    for (int i = blk*NTHR + tid; i < 2*BH; i += NBLK*NTHR) {
        out[524288 + i] = g_dech[i];
        out[655360 + i] = g_decc[i];
    }
}

// ---------------- host launch: ONE graph node ----------------
extern "C" void kernel_launch(void* const* d_in, const int* in_sizes, int n_in,
                              void* d_out, int out_size)
{
    (void)in_sizes; (void)n_in; (void)out_size;
    traj_kernel<<<NBLK, NTHR>>>(
        (const float*)d_in[0],  (const float*)d_in[1],  (const float*)d_in[2],
        (const float*)d_in[3],  (const float*)d_in[4],  (const float*)d_in[5],
        (const float*)d_in[6],  (const float*)d_in[7],  (const float*)d_in[8],
        (const float*)d_in[9],  (const float*)d_in[10], (const float*)d_in[11],
        (const float*)d_in[12], (const float*)d_in[13], (const float*)d_in[14],
        (const float*)d_in[15], (const float*)d_in[16], (float*)d_out);
}

// round 4
// speedup vs baseline: 1.2774x; 1.2774x over previous
#include <cuda_runtime.h>
#include <math.h>

#define B   128
#define T   256
#define H   512
#define H4  2048
#define V   128
#define LW  32
#define SOS 1
#define BH  (B*H)      // 65536
#define NBLK 128
#define NTHR 256

// ---------------- device scratch (static) ----------------
__device__ float g_enc0[(size_t)B*T*2*H];   // [b][t][dir*H+u]
__device__ float g_enc1[(size_t)B*T*2*H];   // [b][t][dir*H+u]
__device__ float g_h0[2*2*BH];              // [parity][dir][b][u]
__device__ float g_h1[2*2*BH];
__device__ float g_c0[2*BH];                // [dir][b][u]
__device__ float g_c1[2*BH];
__device__ float g_dech[2*2*BH];            // [parity][l][b][u]
__device__ float g_decc[2*BH];              // [l][b][u]
__device__ float g_query[B*2*H];
__device__ float g_ctx[B*2*H];
__device__ float g_comb[B*H];
__device__ int   g_tok[B];

__device__ unsigned g_cnt = 0;
__device__ volatile unsigned g_gen = 0;

// ---------------- software grid barrier (all NBLK blocks resident) ----------------
__device__ __forceinline__ void gbar(unsigned &gen)
{
    __syncthreads();
    if (threadIdx.x == 0) {
        __threadfence();
        unsigned t = atomicAdd(&g_cnt, 1u);
        if (t == NBLK - 1u) {
            atomicExch(&g_cnt, 0u);
            __threadfence();
            g_gen = gen + 1u;
        } else {
            while (g_gen == gen) {}
            __threadfence();
        }
    }
    __syncthreads();
    gen++;
}

// ---------------- double-buffered gate GEMM ----------------
// acc += A[64 rows] x W columns {g*512 + u0 + 0..15, g=0..3}
// sh layout: As[2][16][64] (4096 floats) then Bs[2][16][64] (4096 floats)
__device__ __forceinline__ void mm_gate(
    float acc[4][4],
    const float* __restrict__ A, long lda, const int* __restrict__ idx, int m0,
    const float* __restrict__ W, int u0, int K, float* sh)
{
    float (*As)[16][64] = (float (*)[16][64])sh;
    float (*Bs)[16][64] = (float (*)[16][64])(sh + 2048);
    const int tid = threadIdx.x;
    const int ty = tid >> 4, tx = tid & 15;
    const int am = tid >> 2, ak = (tid & 3) * 4;
    long arow = idx ? (long)idx[m0 + am] : (long)(m0 + am);
    const float* Ab = A + arow * lda + ak;
    const int bk  = tid >> 4;
    const int btx = tid & 15;
    const int bcol = (btx >> 2) * H + u0 + (btx & 3) * 4;
    const float* Wb = W + (long)bk * H4 + bcol;

    const int NC = K >> 4;
    float4 av = *(const float4*)(Ab);
    float4 bv = *(const float4*)(Wb);
    As[0][ak+0][am] = av.x; As[0][ak+1][am] = av.y;
    As[0][ak+2][am] = av.z; As[0][ak+3][am] = av.w;
    *(float4*)&Bs[0][bk][btx*4] = bv;
    __syncthreads();
    int cur = 0;
    for (int ch = 0; ch < NC; ch++) {
        if (ch + 1 < NC) {
            av = *(const float4*)(Ab + (ch + 1) * 16);
            bv = *(const float4*)(Wb + (long)(ch + 1) * 16 * H4);
        }
        const float (* __restrict__ Ac)[64] = As[cur];
        const float (* __restrict__ Bc)[64] = Bs[cur];
        #pragma unroll
        for (int k = 0; k < 16; k++) {
            float4 a = *(const float4*)&Ac[k][ty*4];
            float4 b = *(const float4*)&Bc[k][tx*4];
            float aa[4] = {a.x,a.y,a.z,a.w};
            float bb[4] = {b.x,b.y,b.z,b.w};
            #pragma unroll
            for (int i = 0; i < 4; i++)
                #pragma unroll
                for (int j = 0; j < 4; j++)
                    acc[i][j] = fmaf(aa[i], bb[j], acc[i][j]);
        }
        if (ch + 1 < NC) {
            int nxt = cur ^ 1;
            As[nxt][ak+0][am] = av.x; As[nxt][ak+1][am] = av.y;
            As[nxt][ak+2][am] = av.z; As[nxt][ak+3][am] = av.w;
            *(float4*)&Bs[nxt][bk][btx*4] = bv;
            __syncthreads();
            cur = nxt;
        }
    }
    // NOTE: NC is even for all call sites, so the last compute reads buffer 1;
    // a subsequent call's first STS targets buffer 0 -> race-free without a bar.
}

// ---------------- double-buffered plain GEMM: acc += A x W[:, n0..n0+64) -------
__device__ __forceinline__ void mm_plain(
    float acc[4][4],
    const float* __restrict__ A, long lda, int m0,
    const float* __restrict__ W, int ldw, int K, int n0, float* sh)
{
    float (*As)[16][64] = (float (*)[16][64])sh;
    float (*Bs)[16][64] = (float (*)[16][64])(sh + 2048);
    const int tid = threadIdx.x;
    const int ty = tid >> 4, tx = tid & 15;
    const int am = tid >> 2, ak = (tid & 3) * 4;
    const float* Ab = A + (long)(m0 + am) * lda + ak;
    const int bk  = tid >> 4;
    const int btx = tid & 15;
    const float* Wb = W + (long)bk * ldw + n0 + btx * 4;

    const int NC = K >> 4;
    float4 av = *(const float4*)(Ab);
    float4 bv = *(const float4*)(Wb);
    As[0][ak+0][am] = av.x; As[0][ak+1][am] = av.y;
    As[0][ak+2][am] = av.z; As[0][ak+3][am] = av.w;
    *(float4*)&Bs[0][bk][btx*4] = bv;
    __syncthreads();
    int cur = 0;
    for (int ch = 0; ch < NC; ch++) {
        if (ch + 1 < NC) {
            av = *(const float4*)(Ab + (ch + 1) * 16);
            bv = *(const float4*)(Wb + (long)(ch + 1) * 16 * ldw);
        }
        const float (* __restrict__ Ac)[64] = As[cur];
        const float (* __restrict__ Bc)[64] = Bs[cur];
        #pragma unroll
        for (int k = 0; k < 16; k++) {
            float4 a = *(const float4*)&Ac[k][ty*4];
            float4 b = *(const float4*)&Bc[k][tx*4];
            float aa[4] = {a.x,a.y,a.z,a.w};
            float bb[4] = {b.x,b.y,b.z,b.w};
            #pragma unroll
            for (int i = 0; i < 4; i++)
                #pragma unroll
                for (int j = 0; j < 4; j++)
                    acc[i][j] = fmaf(aa[i], bb[j], acc[i][j]);
        }
        if (ch + 1 < NC) {
            int nxt = cur ^ 1;
            As[nxt][ak+0][am] = av.x; As[nxt][ak+1][am] = av.y;
            As[nxt][ak+2][am] = av.z; As[nxt][ak+3][am] = av.w;
            *(float4*)&Bs[nxt][bk][btx*4] = bv;
            __syncthreads();
            cur = nxt;
        }
    }
}

__device__ __forceinline__ float sigm(float v) { return 1.f/(1.f + expf(-v)); }

// ---------------- the single persistent kernel ----------------
__global__ void __launch_bounds__(NTHR, 1)
traj_kernel(const float* __restrict__ x,
            const float* __restrict__ w0ih, const float* __restrict__ w0hh, const float* __restrict__ b0,
            const float* __restrict__ w1ih, const float* __restrict__ w1hh, const float* __restrict__ b1,
            const float* __restrict__ dWih, const float* __restrict__ dWhh, const float* __restrict__ db,
            const float* __restrict__ emb,
            const float* __restrict__ Wq,  const float* __restrict__ bq,
            const float* __restrict__ Wc,  const float* __restrict__ bc,
            const float* __restrict__ Wf,  const float* __restrict__ bfv,
            float* __restrict__ out)
{
    __shared__ float SH[8192];       // GEMM double buffers (32 KB)
    __shared__ float Gs[64][65];     // gate tile / attention scratch (16.6 KB)

    const int blk = blockIdx.x;
    const int tid = threadIdx.x;
    unsigned gen = 0;

    // ---- init: zero states ----
    for (int i = blk*NTHR + tid; i < 2*BH; i += NBLK*NTHR) {
        g_h0[i] = 0.f; g_h1[i] = 0.f;
        g_c0[i] = 0.f; g_c1[i] = 0.f;
    }
    gbar(gen);

    // ---- encoder ----
    for (int layer = 0; layer < 2; layer++) {
        const int dir = blk >> 6;
        const int m0  = ((blk >> 5) & 1) * 64;
        const int u0  = (blk & 31) * 16;
        const int ty = tid >> 4, tx = tid & 15;
        for (int tf = 0; tf < T; tf++) {
            const int t = dir ? (T - 1 - tf) : tf;
            const int po = (tf & 1) * 2 * BH;
            const int pn = ((tf + 1) & 1) * 2 * BH;
            float acc[4][4] = {};
            const float* bias_d;
            if (layer == 0) {
                mm_gate(acc, g_h0 + po + (long)dir*BH, H, nullptr, m0,
                        w0hh + (long)dir*H*H4, u0, H, SH);
                bias_d = b0 + (long)dir*H4;
            } else {
                mm_gate(acc, g_enc0 + (long)t*2*H, (long)T*2*H, nullptr, m0,
                        w1ih + (long)dir*(2*H)*H4, u0, 2*H, SH);
                mm_gate(acc, g_h1 + po + (long)dir*BH, H, nullptr, m0,
                        w1hh + (long)dir*H*H4, u0, H, SH);
                bias_d = b1 + (long)dir*H4;
            }
            #pragma unroll
            for (int i = 0; i < 4; i++) {
                int ml = ty*4 + i;
                float x0 = 0.f, x1 = 0.f;
                if (layer == 0) {
                    int b = m0 + ml;
                    x0 = x[((long)b*T + t)*2 + 0];
                    x1 = x[((long)b*T + t)*2 + 1];
                }
                #pragma unroll
                for (int j = 0; j < 4; j++) {
                    int cg = tx*4 + j;
                    int col = (cg >> 4)*H + u0 + (cg & 15);
                    float v = acc[i][j] + bias_d[col];
                    if (layer == 0) {
                        const float* Wi = w0ih + (long)dir*2*H4;
                        v += x0*Wi[col] + x1*Wi[H4 + col];
                    }
                    Gs[ml][cg] = v;
                }
            }
            __syncthreads();
            float* hN = (layer ? g_h1 : g_h0) + pn + (long)dir*BH;
            float* cB = (layer ? g_c1 : g_c0) + (long)dir*BH;
            float* y  = layer ? g_enc1 : g_enc0;
            #pragma unroll
            for (int r = 0; r < 4; r++) {
                int p  = tid + r*NTHR;
                int ml = p >> 4, ui = p & 15;
                float gi = Gs[ml][ui],      gf = Gs[ml][16+ui];
                float gg = Gs[ml][32+ui],   go = Gs[ml][48+ui];
                int b = m0 + ml, u = u0 + ui;
                long su = (long)b*H + u;
                float cn = sigm(gf)*cB[su] + sigm(gi)*tanhf(gg);
                float hn = sigm(go)*tanhf(cn);
                cB[su] = cn;
                hN[su] = hn;
                y[((long)b*T + t)*(2*H) + dir*H + u] = hn;
            }
            gbar(gen);
        }
    }

    // ---- decoder init ----
    for (int i = blk*NTHR + tid; i < BH; i += NBLK*NTHR) {
        g_dech[i]      = g_h0[i] + g_h0[BH + i];
        g_decc[i]      = g_c0[i] + g_c0[BH + i];
        g_dech[BH + i] = g_h1[i] + g_h1[BH + i];
        g_decc[BH + i] = g_c1[i] + g_c1[BH + i];
    }
    if (blk == 0 && tid < B) g_tok[tid] = SOS;
    gbar(gen);

    const int ty = tid >> 4, tx = tid & 15;

    // ---- decoder: 32 greedy steps ----
    for (int s = 0; s < LW; s++) {
        const int po = (s & 1) * 2 * BH;
        const int pn = ((s + 1) & 1) * 2 * BH;

        for (int l = 0; l < 2; l++) {
            if (blk < 64) {
                const int m0 = (blk >> 5) * 64;
                const int u0 = (blk & 31) * 16;
                float acc[4][4] = {};
                if (l == 0)
                    mm_gate(acc, emb, H, g_tok, m0, dWih, u0, H, SH);
                else
                    mm_gate(acc, g_dech + pn, H, nullptr, m0, dWih + (long)H*H4, u0, H, SH);
                mm_gate(acc, g_dech + po + (long)l*BH, H, nullptr, m0,
                        dWhh + (long)l*H*H4, u0, H, SH);
                const float* bias_d = db + (long)l*H4;
                #pragma unroll
                for (int i = 0; i < 4; i++) {
                    int ml = ty*4 + i;
                    #pragma unroll
                    for (int j = 0; j < 4; j++) {
                        int cg = tx*4 + j;
                        int col = (cg >> 4)*H + u0 + (cg & 15);
                        Gs[ml][cg] = acc[i][j] + bias_d[col];
                    }
                }
                __syncthreads();
                float* hN = g_dech + pn + (long)l*BH;
                float* cB = g_decc + (long)l*BH;
                #pragma unroll
                for (int r = 0; r < 4; r++) {
                    int p  = tid + r*NTHR;
                    int ml = p >> 4, ui = p & 15;
                    float gi = Gs[ml][ui],    gf = Gs[ml][16+ui];
                    float gg = Gs[ml][32+ui], go = Gs[ml][48+ui];
                    long su = (long)(m0 + ml)*H + (u0 + ui);
                    float cn = sigm(gf)*cB[su] + sigm(gi)*tanhf(gg);
                    float hn = sigm(go)*tanhf(cn);
                    cB[su] = cn;
                    hN[su] = hn;
                }
            }
            gbar(gen);
        }

        // query = h1_new @ Wq + bq
        if (blk < 32) {
            const int m0 = (blk >> 4) * 64;
            const int n0 = (blk & 15) * 64;
            float acc[4][4] = {};
            mm_plain(acc, g_dech + pn + BH, H, m0, Wq, 2*H, H, n0, SH);
            #pragma unroll
            for (int i = 0; i < 4; i++) {
                int m = m0 + ty*4 + i;
                #pragma unroll
                for (int j = 0; j < 4; j++) {
                    int n = n0 + tx*4 + j;
                    g_query[(long)m*(2*H) + n] = acc[i][j] + bq[n];
                }
            }
        }
        gbar(gen);

        // attention per batch
        {
            const int b = blk;
            float* sm = &Gs[0][0];
            float* qs  = sm;
            float* sc  = sm + 1024;
            float* red = sm + 1280;
            for (int e = tid; e < 2*H; e += NTHR) qs[e] = g_query[(long)b*2*H + e];
            __syncthreads();
            const int warp = tid >> 5, lane = tid & 31;
            for (int tb = 0; tb < T; tb += 8) {
                int t = tb + warp;
                const float* row = g_enc1 + ((long)b*T + t)*(2*H);
                float p = 0.f;
                for (int e = lane; e < 2*H; e += 32) p = fmaf(row[e], qs[e], p);
                #pragma unroll
                for (int o = 16; o; o >>= 1) p += __shfl_xor_sync(0xffffffffu, p, o);
                if (lane == 0) sc[t] = p;
            }
            __syncthreads();
            float v = sc[tid];
            red[tid] = v; __syncthreads();
            for (int o = 128; o; o >>= 1) {
                if (tid < o) red[tid] = fmaxf(red[tid], red[tid + o]);
                __syncthreads();
            }
            float mx = red[0]; __syncthreads();
            float e = expf(v - mx);
            red[tid] = e; __syncthreads();
            for (int o = 128; o; o >>= 1) {
                if (tid < o) red[tid] += red[tid + o];
                __syncthreads();
            }
            float a = e / red[0];
            sc[tid] = a;
            out[786432 + ((long)b*T + tid)*LW + s] = a;
            __syncthreads();
            for (int ec = tid; ec < 2*H; ec += NTHR) {
                float accv = 0.f;
                const float* base = g_enc1 + ((long)b*T)*(2*H) + ec;
                for (int t = 0; t < T; t++) accv = fmaf(sc[t], base[(long)t*2*H], accv);
                g_ctx[(long)b*2*H + ec] = accv;
            }
        }
        gbar(gen);

        // combined = [h1 | ctx] @ Wc + bc
        if (blk < 16) {
            const int m0 = (blk >> 3) * 64;
            const int n0 = (blk & 7) * 64;
            float acc[4][4] = {};
            mm_plain(acc, g_dech + pn + BH, H, m0, Wc, H, H, n0, SH);
            mm_plain(acc, g_ctx, 2*H, m0, Wc + (long)H*H, H, 2*H, n0, SH);
            #pragma unroll
            for (int i = 0; i < 4; i++) {
                int m = m0 + ty*4 + i;
                #pragma unroll
                for (int j = 0; j < 4; j++) {
                    int n = n0 + tx*4 + j;
                    g_comb[(long)m*H + n] = acc[i][j] + bc[n];
                }
            }
        }
        gbar(gen);

        // logits + argmax
        {
            const int b = blk;
            float* sm = &Gs[0][0];
            float* cs = sm;
            float* sv = sm + 512;
            int*   si = (int*)(sm + 640);
            for (int k = tid; k < H; k += NTHR) cs[k] = g_comb[(long)b*H + k];
            __syncthreads();
            if (tid < V) {
                float acc = bfv[tid];
                for (int k = 0; k < H; k++) acc = fmaf(cs[k], Wf[(long)k*V + tid], acc);
                out[((long)b*LW + s)*V + tid] = acc;
                sv[tid] = acc; si[tid] = tid;
            }
            __syncthreads();
            for (int o = 64; o; o >>= 1) {
                if (tid < o) {
                    float v2 = sv[tid + o]; int i2 = si[tid + o];
                    if (v2 > sv[tid] || (v2 == sv[tid] && i2 < si[tid])) {
                        sv[tid] = v2; si[tid] = i2;
                    }
                }
                __syncthreads();
            }
            if (tid == 0) g_tok[b] = si[0];
        }
        gbar(gen);
    }

    // ---- final states ----
    for (int i = blk*NTHR + tid; i < 2*BH; i += NBLK*NTHR) {
        out[524288 + i] = g_dech[i];
        out[655360 + i] = g_decc[i];
    }
}

// ---------------- host launch: ONE graph node ----------------
extern "C" void kernel_launch(void* const* d_in, const int* in_sizes, int n_in,
                              void* d_out, int out_size)
{
    (void)in_sizes; (void)n_in; (void)out_size;
    traj_kernel<<<NBLK, NTHR>>>(
        (const float*)d_in[0],  (const float*)d_in[1],  (const float*)d_in[2],
        (const float*)d_in[3],  (const float*)d_in[4],  (const float*)d_in[5],
        (const float*)d_in[6],  (const float*)d_in[7],  (const float*)d_in[8],
        (const float*)d_in[9],  (const float*)d_in[10], (const float*)d_in[11],
        (const float*)d_in[12], (const float*)d_in[13], (const float*)d_in[14],
        (const float*)d_in[15], (const float*)d_in[16], (float*)d_out);
}

// round 5
// speedup vs baseline: 1.3278x; 1.0394x over previous
#include <cuda_runtime.h>
#include <math.h>

#define B   128
#define T   256
#define H   512
#define H4  2048
#define V   128
#define LW  32
#define SOS 1
#define BH  (B*H)      // 65536
#define NBLK 128
#define NTHR 256

// ---------------- device scratch (static) ----------------
__device__ float g_enc0[(size_t)B*T*2*H];   // [b][t][dir*H+u]
__device__ float g_enc1[(size_t)B*T*2*H];   // [b][t][dir*H+u]
__device__ float g_h0[2*2*BH];              // [parity][dir][b][u]
__device__ float g_h1[2*2*BH];
__device__ float g_c0[2*BH];                // [dir][b][u]
__device__ float g_c1[2*BH];
__device__ float g_dech[2*2*BH];            // [parity][l][b][u]
__device__ float g_decc[2*BH];              // [l][b][u]
__device__ float g_query[B*2*H];
__device__ float g_ctx[B*2*H];
__device__ float g_comb[B*H];
__device__ int   g_tok[B];

__device__ unsigned g_cnt = 0;
__device__ volatile unsigned g_gen = 0;

// ---------------- software grid barrier (all NBLK blocks resident) ----------------
__device__ __forceinline__ void gbar(unsigned &gen)
{
    __syncthreads();
    if (threadIdx.x == 0) {
        __threadfence();
        unsigned t = atomicAdd(&g_cnt, 1u);
        if (t == NBLK - 1u) {
            atomicExch(&g_cnt, 0u);
            __threadfence();
            g_gen = gen + 1u;
        } else {
            while (g_gen == gen) {}
            __threadfence();
        }
    }
    __syncthreads();
    gen++;
}

// ---------------- double-buffered gate GEMM ----------------
// acc += A[64 rows] x W columns {g*512 + u0 + 0..15, g=0..3}
// sh layout: As[2][16][64] (4096 floats) then Bs[2][16][64] (4096 floats)
__device__ __forceinline__ void mm_gate(
    float acc[4][4],
    const float* __restrict__ A, long lda, const int* __restrict__ idx, int m0,
    const float* __restrict__ W, int u0, int K, float* sh)
{
    float (*As)[16][64] = (float (*)[16][64])sh;
    float (*Bs)[16][64] = (float (*)[16][64])(sh + 2048);
    const int tid = threadIdx.x;
    const int ty = tid >> 4, tx = tid & 15;
    const int am = tid >> 2, ak = (tid & 3) * 4;
    long arow = idx ? (long)idx[m0 + am] : (long)(m0 + am);
    const float* Ab = A + arow * lda + ak;
    const int bk  = tid >> 4;
    const int btx = tid & 15;
    const int bcol = (btx >> 2) * H + u0 + (btx & 3) * 4;
    const float* Wb = W + (long)bk * H4 + bcol;

    const int NC = K >> 4;
    float4 av = *(const float4*)(Ab);
    float4 bv = *(const float4*)(Wb);
    As[0][ak+0][am] = av.x; As[0][ak+1][am] = av.y;
    As[0][ak+2][am] = av.z; As[0][ak+3][am] = av.w;
    *(float4*)&Bs[0][bk][btx*4] = bv;
    __syncthreads();
    int cur = 0;
    for (int ch = 0; ch < NC; ch++) {
        if (ch + 1 < NC) {
            av = *(const float4*)(Ab + (ch + 1) * 16);
            bv = *(const float4*)(Wb + (long)(ch + 1) * 16 * H4);
        }
        const float (* __restrict__ Ac)[64] = As[cur];
        const float (* __restrict__ Bc)[64] = Bs[cur];
        #pragma unroll
        for (int k = 0; k < 16; k++) {
            float4 a = *(const float4*)&Ac[k][ty*4];
            float4 b = *(const float4*)&Bc[k][tx*4];
            float aa[4] = {a.x,a.y,a.z,a.w};
            float bb[4] = {b.x,b.y,b.z,b.w};
            #pragma unroll
            for (int i = 0; i < 4; i++)
                #pragma unroll
                for (int j = 0; j < 4; j++)
                    acc[i][j] = fmaf(aa[i], bb[j], acc[i][j]);
        }
        if (ch + 1 < NC) {
            int nxt = cur ^ 1;
            As[nxt][ak+0][am] = av.x; As[nxt][ak+1][am] = av.y;
            As[nxt][ak+2][am] = av.z; As[nxt][ak+3][am] = av.w;
            *(float4*)&Bs[nxt][bk][btx*4] = bv;
            __syncthreads();
            cur = nxt;
        }
    }
    // NOTE: NC is even for all call sites, so the last compute reads buffer 1;
    // a subsequent call's first STS targets buffer 0 -> race-free without a bar.
}

// ---------------- double-buffered plain GEMM: acc += A x W[:, n0..n0+64) -------
__device__ __forceinline__ void mm_plain(
    float acc[4][4],
    const float* __restrict__ A, long lda, int m0,
    const float* __restrict__ W, int ldw, int K, int n0, float* sh)
{
    float (*As)[16][64] = (float (*)[16][64])sh;
    float (*Bs)[16][64] = (float (*)[16][64])(sh + 2048);
    const int tid = threadIdx.x;
    const int ty = tid >> 4, tx = tid & 15;
    const int am = tid >> 2, ak = (tid & 3) * 4;
    const float* Ab = A + (long)(m0 + am) * lda + ak;
    const int bk  = tid >> 4;
    const int btx = tid & 15;
    const float* Wb = W + (long)bk * ldw + n0 + btx * 4;

    const int NC = K >> 4;
    float4 av = *(const float4*)(Ab);
    float4 bv = *(const float4*)(Wb);
    As[0][ak+0][am] = av.x; As[0][ak+1][am] = av.y;
    As[0][ak+2][am] = av.z; As[0][ak+3][am] = av.w;
    *(float4*)&Bs[0][bk][btx*4] = bv;
    __syncthreads();
    int cur = 0;
    for (int ch = 0; ch < NC; ch++) {
        if (ch + 1 < NC) {
            av = *(const float4*)(Ab + (ch + 1) * 16);
            bv = *(const float4*)(Wb + (long)(ch + 1) * 16 * ldw);
        }
        const float (* __restrict__ Ac)[64] = As[cur];
        const float (* __restrict__ Bc)[64] = Bs[cur];
        #pragma unroll
        for (int k = 0; k < 16; k++) {
            float4 a = *(const float4*)&Ac[k][ty*4];
            float4 b = *(const float4*)&Bc[k][tx*4];
            float aa[4] = {a.x,a.y,a.z,a.w};
            float bb[4] = {b.x,b.y,b.z,b.w};
            #pragma unroll
            for (int i = 0; i < 4; i++)
                #pragma unroll
                for (int j = 0; j < 4; j++)
                    acc[i][j] = fmaf(aa[i], bb[j], acc[i][j]);
        }
        if (ch + 1 < NC) {
            int nxt = cur ^ 1;
            As[nxt][ak+0][am] = av.x; As[nxt][ak+1][am] = av.y;
            As[nxt][ak+2][am] = av.z; As[nxt][ak+3][am] = av.w;
            *(float4*)&Bs[nxt][bk][btx*4] = bv;
            __syncthreads();
            cur = nxt;
        }
    }
}

__device__ __forceinline__ float sigm(float v) { return 1.f/(1.f + expf(-v)); }

// ---------------- the single persistent kernel ----------------
__global__ void __launch_bounds__(NTHR, 1)
traj_kernel(const float* __restrict__ x,
            const float* __restrict__ w0ih, const float* __restrict__ w0hh, const float* __restrict__ b0,
            const float* __restrict__ w1ih, const float* __restrict__ w1hh, const float* __restrict__ b1,
            const float* __restrict__ dWih, const float* __restrict__ dWhh, const float* __restrict__ db,
            const float* __restrict__ emb,
            const float* __restrict__ Wq,  const float* __restrict__ bq,
            const float* __restrict__ Wc,  const float* __restrict__ bc,
            const float* __restrict__ Wf,  const float* __restrict__ bfv,
            float* __restrict__ out)
{
    __shared__ float SH[8192];       // GEMM double buffers (32 KB)
    __shared__ float Gs[64][65];     // gate tile / attention scratch (16.6 KB)

    const int blk = blockIdx.x;
    const int tid = threadIdx.x;
    unsigned gen = 0;

    // ---- init: zero states ----
    for (int i = blk*NTHR + tid; i < 2*BH; i += NBLK*NTHR) {
        g_h0[i] = 0.f; g_h1[i] = 0.f;
        g_c0[i] = 0.f; g_c1[i] = 0.f;
    }
    gbar(gen);

    // ---- encoder ----
    for (int layer = 0; layer < 2; layer++) {
        const int dir = blk >> 6;
        const int m0  = ((blk >> 5) & 1) * 64;
        const int u0  = (blk & 31) * 16;
        const int ty = tid >> 4, tx = tid & 15;
        for (int tf = 0; tf < T; tf++) {
            const int t = dir ? (T - 1 - tf) : tf;
            const int po = (tf & 1) * 2 * BH;
            const int pn = ((tf + 1) & 1) * 2 * BH;
            float acc[4][4] = {};
            const float* bias_d;
            if (layer == 0) {
                mm_gate(acc, g_h0 + po + (long)dir*BH, H, nullptr, m0,
                        w0hh + (long)dir*H*H4, u0, H, SH);
                bias_d = b0 + (long)dir*H4;
            } else {
                mm_gate(acc, g_enc0 + (long)t*2*H, (long)T*2*H, nullptr, m0,
                        w1ih + (long)dir*(2*H)*H4, u0, 2*H, SH);
                mm_gate(acc, g_h1 + po + (long)dir*BH, H, nullptr, m0,
                        w1hh + (long)dir*H*H4, u0, H, SH);
                bias_d = b1 + (long)dir*H4;
            }
            #pragma unroll
            for (int i = 0; i < 4; i++) {
                int ml = ty*4 + i;
                float x0 = 0.f, x1 = 0.f;
                if (layer == 0) {
                    int b = m0 + ml;
                    x0 = x[((long)b*T + t)*2 + 0];
                    x1 = x[((long)b*T + t)*2 + 1];
                }
                #pragma unroll
                for (int j = 0; j < 4; j++) {
                    int cg = tx*4 + j;
                    int col = (cg >> 4)*H + u0 + (cg & 15);
                    float v = acc[i][j] + bias_d[col];
                    if (layer == 0) {
                        const float* Wi = w0ih + (long)dir*2*H4;
                        v += x0*Wi[col] + x1*Wi[H4 + col];
                    }
                    Gs[ml][cg] = v;
                }
            }
            __syncthreads();
            float* hN = (layer ? g_h1 : g_h0) + pn + (long)dir*BH;
            float* cB = (layer ? g_c1 : g_c0) + (long)dir*BH;
            float* y  = layer ? g_enc1 : g_enc0;
            #pragma unroll
            for (int r = 0; r < 4; r++) {
                int p  = tid + r*NTHR;
                int ml = p >> 4, ui = p & 15;
                float gi = Gs[ml][ui],      gf = Gs[ml][16+ui];
                float gg = Gs[ml][32+ui],   go = Gs[ml][48+ui];
                int b = m0 + ml, u = u0 + ui;
                long su = (long)b*H + u;
                float cn = sigm(gf)*cB[su] + sigm(gi)*tanhf(gg);
                float hn = sigm(go)*tanhf(cn);
                cB[su] = cn;
                hN[su] = hn;
                y[((long)b*T + t)*(2*H) + dir*H + u] = hn;
            }
            gbar(gen);
        }
    }

    // ---- decoder init ----
    for (int i = blk*NTHR + tid; i < BH; i += NBLK*NTHR) {
        g_dech[i]      = g_h0[i] + g_h0[BH + i];
        g_decc[i]      = g_c0[i] + g_c0[BH + i];
        g_dech[BH + i] = g_h1[i] + g_h1[BH + i];
        g_decc[BH + i] = g_c1[i] + g_c1[BH + i];
    }
    if (blk == 0 && tid < B) g_tok[tid] = SOS;
    gbar(gen);

    const int ty = tid >> 4, tx = tid & 15;

    // ---- decoder: 32 greedy steps ----
    for (int s = 0; s < LW; s++) {
        const int po = (s & 1) * 2 * BH;
        const int pn = ((s + 1) & 1) * 2 * BH;

        for (int l = 0; l < 2; l++) {
            if (blk < 64) {
                const int m0 = (blk >> 5) * 64;
                const int u0 = (blk & 31) * 16;
                float acc[4][4] = {};
                if (l == 0)
                    mm_gate(acc, emb, H, g_tok, m0, dWih, u0, H, SH);
                else
                    mm_gate(acc, g_dech + pn, H, nullptr, m0, dWih + (long)H*H4, u0, H, SH);
                mm_gate(acc, g_dech + po + (long)l*BH, H, nullptr, m0,
                        dWhh + (long)l*H*H4, u0, H, SH);
                const float* bias_d = db + (long)l*H4;
                #pragma unroll
                for (int i = 0; i < 4; i++) {
                    int ml = ty*4 + i;
                    #pragma unroll
                    for (int j = 0; j < 4; j++) {
                        int cg = tx*4 + j;
                        int col = (cg >> 4)*H + u0 + (cg & 15);
                        Gs[ml][cg] = acc[i][j] + bias_d[col];
                    }
                }
                __syncthreads();
                float* hN = g_dech + pn + (long)l*BH;
                float* cB = g_decc + (long)l*BH;
                #pragma unroll
                for (int r = 0; r < 4; r++) {
                    int p  = tid + r*NTHR;
                    int ml = p >> 4, ui = p & 15;
                    float gi = Gs[ml][ui],    gf = Gs[ml][16+ui];
                    float gg = Gs[ml][32+ui], go = Gs[ml][48+ui];
                    long su = (long)(m0 + ml)*H + (u0 + ui);
                    float cn = sigm(gf)*cB[su] + sigm(gi)*tanhf(gg);
                    float hn = sigm(go)*tanhf(cn);
                    cB[su] = cn;
                    hN[su] = hn;
                }
            }
            gbar(gen);
        }

        // query = h1_new @ Wq + bq
        if (blk < 32) {
            const int m0 = (blk >> 4) * 64;
            const int n0 = (blk & 15) * 64;
            float acc[4][4] = {};
            mm_plain(acc, g_dech + pn + BH, H, m0, Wq, 2*H, H, n0, SH);
            #pragma unroll
            for (int i = 0; i < 4; i++) {
                int m = m0 + ty*4 + i;
                #pragma unroll
                for (int j = 0; j < 4; j++) {
                    int n = n0 + tx*4 + j;
                    g_query[(long)m*(2*H) + n] = acc[i][j] + bq[n];
                }
            }
        }
        gbar(gen);

        // attention per batch
        {
            const int b = blk;
            float* sm = &Gs[0][0];
            float* qs  = sm;
            float* sc  = sm + 1024;
            float* red = sm + 1280;
            for (int e = tid; e < 2*H; e += NTHR) qs[e] = g_query[(long)b*2*H + e];
            __syncthreads();
            const int warp = tid >> 5, lane = tid & 31;
            for (int tb = 0; tb < T; tb += 8) {
                int t = tb + warp;
                const float* row = g_enc1 + ((long)b*T + t)*(2*H);
                float p = 0.f;
                for (int e = lane; e < 2*H; e += 32) p = fmaf(row[e], qs[e], p);
                #pragma unroll
                for (int o = 16; o; o >>= 1) p += __shfl_xor_sync(0xffffffffu, p, o);
                if (lane == 0) sc[t] = p;
            }
            __syncthreads();
            float v = sc[tid];
            red[tid] = v; __syncthreads();
            for (int o = 128; o; o >>= 1) {
                if (tid < o) red[tid] = fmaxf(red[tid], red[tid + o]);
                __syncthreads();
            }
            float mx = red[0]; __syncthreads();
            float e = expf(v - mx);
            red[tid] = e; __syncthreads();
            for (int o = 128; o; o >>= 1) {
                if (tid < o) red[tid] += red[tid + o];
                __syncthreads();
            }
            float a = e / red[0];
            sc[tid] = a;
            out[786432 + ((long)b*T + tid)*LW + s] = a;
            __syncthreads();
            for (int ec = tid; ec < 2*H; ec += NTHR) {
                float accv = 0.f;
                const float* base = g_enc1 + ((long)b*T)*(2*H) + ec;
                for (int t = 0; t < T; t++) accv = fmaf(sc[t], base[(long)t*2*H], accv);
                g_ctx[(long)b*2*H + ec] = accv;
            }
        }
        gbar(gen);

        // combined = [h1 | ctx] @ Wc + bc
        if (blk < 16) {
            const int m0 = (blk >> 3) * 64;
            const int n0 = (blk & 7) * 64;
            float acc[4][4] = {};
            mm_plain(acc, g_dech + pn + BH, H, m0, Wc, H, H, n0, SH);
            mm_plain(acc, g_ctx, 2*H, m0, Wc + (long)H*H, H, 2*H, n0, SH);
            #pragma unroll
            for (int i = 0; i < 4; i++) {
                int m = m0 + ty*4 + i;
                #pragma unroll
                for (int j = 0; j < 4; j++) {
                    int n = n0 + tx*4 + j;
                    g_comb[(long)m*H + n] = acc[i][j] + bc[n];
                }
            }
        }
        gbar(gen);

        // logits + argmax
        {
            const int b = blk;
            float* sm = &Gs[0][0];
            float* cs = sm;
            float* sv = sm + 512;
            int*   si = (int*)(sm + 640);
            for (int k = tid; k < H; k += NTHR) cs[k] = g_comb[(long)b*H + k];
            __syncthreads();
            if (tid < V) {
                float acc = bfv[tid];
                for (int k = 0; k < H; k++) acc = fmaf(cs[k], Wf[(long)k*V + tid], acc);
                out[((long)b*LW + s)*V + tid] = acc;
                sv[tid] = acc; si[tid] = tid;
            }
            __syncthreads();
            for (int o = 64; o; o >>= 1) {
                if (tid < o) {
                    float v2 = sv[tid + o]; int i2 = si[tid + o];
                    if (v2 > sv[tid] || (v2 == sv[tid] && i2 < si[tid])) {
                        sv[tid] = v2; si[tid] = i2;
                    }
                }
                __syncthreads();
            }
            if (tid == 0) g_tok[b] = si[0];
        }
        gbar(gen);
    }

    // ---- final states ----
    for (int i = blk*NTHR + tid; i < 2*BH; i += NBLK*NTHR) {
        out[524288 + i] = g_dech[i];
        out[655360 + i] = g_decc[i];
    }
}

// ---------------- host launch: ONE graph node ----------------
extern "C" void kernel_launch(void* const* d_in, const int* in_sizes, int n_in,
                              void* d_out, int out_size)
{
    (void)in_sizes; (void)n_in; (void)out_size;
    traj_kernel<<<NBLK, NTHR>>>(
        (const float*)d_in[0],  (const float*)d_in[1],  (const float*)d_in[2],
        (const float*)d_in[3],  (const float*)d_in[4],  (const float*)d_in[5],
        (const float*)d_in[6],  (const float*)d_in[7],  (const float*)d_in[8],
        (const float*)d_in[9],  (const float*)d_in[10], (const float*)d_in[11],
        (const float*)d_in[12], (const float*)d_in[13], (const float*)d_in[14],
        (const float*)d_in[15], (const float*)d_in[16], (float*)d_out);
}